// round 11
// baseline (speedup 1.0000x reference)
#include <cuda_runtime.h>
#include <cstdint>

#define H 512
#define TOT (16*256*256)
#define HALF (TOT/2)
#define SCALE_INV 0.1f
#define STRENGTH 5.0f

typedef unsigned long long u64;

// ---------- packed f32x2 helpers ----------
__device__ __forceinline__ u64 pk(float lo, float hi) {
    u64 r; asm("mov.b64 %0, {%1, %2};" : "=l"(r) : "f"(lo), "f"(hi)); return r;
}
__device__ __forceinline__ void upk(u64 v, float& lo, float& hi) {
    asm("mov.b64 {%0, %1}, %2;" : "=f"(lo), "=f"(hi) : "l"(v));
}
__device__ __forceinline__ u64 fma2(u64 a, u64 b, u64 c) {
    u64 d; asm("fma.rn.f32x2 %0, %1, %2, %3;" : "=l"(d) : "l"(a), "l"(b), "l"(c)); return d;
}
__device__ __forceinline__ u64 add2(u64 a, u64 b) {
    u64 d; asm("add.rn.f32x2 %0, %1, %2;" : "=l"(d) : "l"(a), "l"(b)); return d;
}
__device__ __forceinline__ u64 cos2(u64 v) {
    float lo, hi; upk(v, lo, hi);
    return pk(__cosf(lo), __cosf(hi));
}
__device__ __forceinline__ u64 xor1(u64 v) {
    return __shfl_xor_sync(0xFFFFFFFFu, v, 1);
}

// ---------- prelude results ----------
__device__ float g_A[4];
__device__ __align__(8) float g_bns[32];
__device__ __align__(8) float g_bno[32];

__global__ void prelude_kernel(const float* __restrict__ gen,
                               const float* __restrict__ gam,
                               const float* __restrict__ bet,
                               const float* __restrict__ mean,
                               const float* __restrict__ var) {
    int t = threadIdx.x;
    if (t == 0) {
        double m0 = gen[0], m1 = gen[1], m2 = gen[2], m3 = gen[3];
        double a0 = 1.0, a1 = 0.0, a2 = 0.0, a3 = 1.0;
        double t0 = 1.0, t1 = 0.0, t2 = 0.0, t3 = 1.0;
        for (int k = 1; k <= 18; k++) {
            double n0 = (t0 * m0 + t1 * m2) / k;
            double n1 = (t0 * m1 + t1 * m3) / k;
            double n2 = (t2 * m0 + t3 * m2) / k;
            double n3 = (t2 * m1 + t3 * m3) / k;
            t0 = n0; t1 = n1; t2 = n2; t3 = n3;
            a0 += n0; a1 += n1; a2 += n2; a3 += n3;
        }
        g_A[0] = (float)a0; g_A[1] = (float)a1;
        g_A[2] = (float)a2; g_A[3] = (float)a3;
    }
    if (t < 32) {
        float s = gam[t] * rsqrtf(var[t] + 0.001f);
        g_bns[t] = s;
        g_bno[t] = bet[t] - mean[t] * s;
    }
}

// ---------- bilinear sample ----------
__device__ __forceinline__ float bil(const float* __restrict__ img, float r, float c) {
    r = fminf(fmaxf(r, 0.0f), (float)(H - 1));
    c = fminf(fmaxf(c, 0.0f), (float)(H - 1));
    float rf = floorf(r), cf = floorf(c);
    int r0 = (int)rf, c0 = (int)cf;
    int r1 = min(r0 + 1, H - 1), c1 = min(c0 + 1, H - 1);
    float wr = r - rf, wc = c - cf;
    float v00 = __ldg(img + r0 * H + c0);
    float v01 = __ldg(img + r0 * H + c1);
    float v10 = __ldg(img + r1 * H + c0);
    float v11 = __ldg(img + r1 * H + c1);
    float top = v00 + wc * (v01 - v00);
    float bot = v10 + wc * (v11 - v10);
    return top + wr * (bot - top);
}

// ---------- main kernel ----------
// Thread-pair (t, t^1) cooperates on 4 pixels (each thread owns 2: M = mine,
// P = partner's, coords exchanged via shfl).
// Layer1 COLUMN-split: thread h computes cols [16h,16h+16) for all 4 px
//   -> reads only half of w1. z stays local (it IS this thread's k-half below).
// Layer2 K-split: thread h sums k in [16h,16h+16) for all 4 px over 4-col
//   passes (k-pair f32x2 lanes, z used packed, no dup movs); partials for
//   partner's px returned via shfl_xor, fused BN/cos/wf epilogue on own px.
#define BLK 128
__global__ __launch_bounds__(BLK, 4)
void rmodel_kernel(const float* __restrict__ x,
                   const float* __restrict__ trans,
                   const float* __restrict__ w0, const float* __restrict__ b0,
                   const float* __restrict__ w1, const float* __restrict__ b1,
                   const float* __restrict__ w2, const float* __restrict__ b2,
                   const float* __restrict__ wf,
                   const float* __restrict__ img,
                   float* __restrict__ out) {
    __shared__ ulonglong2 s_w1[256];    // [k*8+q] = w1 row k, cols 4q..4q+3
    __shared__ ulonglong2 s_w2p[256];   // [((p*8+m)*2+jp)*2+hh]:
                                        //   k-pair {2(8hh+m), +1}, cols 4p+2jp..+1
    __shared__ ulonglong2 s_l0[32];     // [k]: .x = dup w0[0][k], .y = dup w0[1][k]
    __shared__ u64 s_l0b[32];           // dup b0[k]
    __shared__ u64 s_b1[16];            // {b1[2t], b1[2t+1]}
    __shared__ float s_b2s[32];         // b2[j]
    __shared__ u64 s_bn2[32];           // {bns[j], bno[j]}
    __shared__ u64 s_wf[32];            // {wf[j][0], wf[j][1]}

    int tid = threadIdx.x;
    int h = tid & 1;
    {
        const ulonglong2* gw1 = (const ulonglong2*)w1;
        for (int e = tid; e < 256; e += BLK) {
            s_w1[e] = gw1[e];
            int hh = e & 1, jp = (e >> 1) & 1, m = (e >> 2) & 7, p = e >> 5;
            int k0 = 16 * hh + 2 * m;
            int j0 = 4 * p + 2 * jp;
            s_w2p[e] = make_ulonglong2(
                pk(w2[k0 * 32 + j0],     w2[(k0 + 1) * 32 + j0]),
                pk(w2[k0 * 32 + j0 + 1], w2[(k0 + 1) * 32 + j0 + 1]));
        }
        if (tid < 32) {
            float wa = w0[tid], wb = w0[32 + tid], bb = b0[tid];
            s_l0[tid] = make_ulonglong2(pk(wa, wa), pk(wb, wb));
            s_l0b[tid] = pk(bb, bb);
            s_b2s[tid] = b2[tid];
            s_bn2[tid] = pk(g_bns[tid], g_bno[tid]);
            s_wf[tid]  = ((const u64*)wf)[tid];
        }
        if (tid < 16) s_b1[tid] = ((const u64*)b1)[tid];
    }
    __syncthreads();

    int i = blockIdx.x * BLK + tid;           // my pixels (i, i+HALF)
    int ib = i + HALF;

    float xa0 = __ldg(x + 3 * i),  xa1 = __ldg(x + 3 * i + 1);
    float xb0 = __ldg(x + 3 * ib), xb1 = __ldg(x + 3 * ib + 1);

    float A0 = g_A[0], A1 = g_A[1], A2 = g_A[2], A3 = g_A[3];
    float t0 = __ldg(trans), t1 = __ldg(trans + 1);

    float ca0 = fmaf(A0, xa0, fmaf(A1, xa1, t0));
    float ca1 = fmaf(A2, xa0, fmaf(A3, xa1, t1));
    float cb0 = fmaf(A0, xb0, fmaf(A1, xb1, t0));
    float cb1 = fmaf(A2, xb0, fmaf(A3, xb1, t1));

    // my scaled coords, lanes = {pxA, pxB}; partner's via shfl
    u64 pa0 = pk(ca0 * SCALE_INV, cb0 * SCALE_INV);
    u64 pa1 = pk(ca1 * SCALE_INV, cb1 * SCALE_INV);
    u64 qa0 = xor1(pa0);
    u64 qa1 = xor1(pa1);

    // ---- layer 1: my 16 columns (8 col-pairs) for all 4 px ----
    u64 accM[2][8], accP[2][8];
    #pragma unroll
    for (int cp = 0; cp < 8; cp++) {
        u64 b = s_b1[8 * h + cp];
        accM[0][cp] = b; accM[1][cp] = b;
        accP[0][cp] = b; accP[1][cp] = b;
    }

    #pragma unroll 4
    for (int k = 0; k < 32; k++) {
        ulonglong2 w0k = s_l0[k];
        u64 b0k = s_l0b[k];
        u64 argM = fma2(pa0, w0k.x, fma2(pa1, w0k.y, b0k));
        u64 argP = fma2(qa0, w0k.x, fma2(qa1, w0k.y, b0k));
        float mA, mB, pA, pB;
        upk(argM, mA, mB); upk(argP, pA, pB);
        float yMA = __cosf(mA), yMB = __cosf(mB);
        float yPA = __cosf(pA), yPB = __cosf(pB);
        u64 dM0 = pk(yMA, yMA), dM1 = pk(yMB, yMB);
        u64 dP0 = pk(yPA, yPA), dP1 = pk(yPB, yPB);
        #pragma unroll
        for (int qq = 0; qq < 4; qq++) {
            ulonglong2 w = s_w1[k * 8 + 4 * h + qq];
            accM[0][2 * qq]     = fma2(dM0, w.x, accM[0][2 * qq]);
            accM[1][2 * qq]     = fma2(dM1, w.x, accM[1][2 * qq]);
            accP[0][2 * qq]     = fma2(dP0, w.x, accP[0][2 * qq]);
            accP[1][2 * qq]     = fma2(dP1, w.x, accP[1][2 * qq]);
            accM[0][2 * qq + 1] = fma2(dM0, w.y, accM[0][2 * qq + 1]);
            accM[1][2 * qq + 1] = fma2(dM1, w.y, accM[1][2 * qq + 1]);
            accP[0][2 * qq + 1] = fma2(dP0, w.y, accP[0][2 * qq + 1]);
            accP[1][2 * qq + 1] = fma2(dP1, w.y, accP[1][2 * qq + 1]);
        }
    }

    // z for my col-half (= my k-half for layer2), all 4 px, packed pairs
    u64 zM[2][8], zP[2][8];
    #pragma unroll
    for (int m = 0; m < 8; m++) {
        zM[0][m] = cos2(accM[0][m]);
        zM[1][m] = cos2(accM[1][m]);
        zP[0][m] = cos2(accP[0][m]);
        zP[1][m] = cos2(accP[1][m]);
    }

    // ---- layer 2: k-split partials, 8 passes of 4 columns ----
    u64 dA = 0ull, dB = 0ull;
    for (int p = 0; p < 8; p++) {
        u64 pM[2][4], pP[2][4];
        #pragma unroll
        for (int c = 0; c < 4; c++) {
            pM[0][c] = 0ull; pM[1][c] = 0ull;
            pP[0][c] = 0ull; pP[1][c] = 0ull;
        }
        const ulonglong2* wb = &s_w2p[(p * 8) * 4 + h];
        #pragma unroll
        for (int m = 0; m < 8; m++) {
            ulonglong2 wA = wb[m * 4];       // cols 4p, 4p+1
            ulonglong2 wB = wb[m * 4 + 2];   // cols 4p+2, 4p+3
            u64 z0 = zM[0][m], z1 = zM[1][m];
            u64 z2 = zP[0][m], z3 = zP[1][m];
            pM[0][0] = fma2(z0, wA.x, pM[0][0]);
            pM[0][1] = fma2(z0, wA.y, pM[0][1]);
            pM[0][2] = fma2(z0, wB.x, pM[0][2]);
            pM[0][3] = fma2(z0, wB.y, pM[0][3]);
            pM[1][0] = fma2(z1, wA.x, pM[1][0]);
            pM[1][1] = fma2(z1, wA.y, pM[1][1]);
            pM[1][2] = fma2(z1, wB.x, pM[1][2]);
            pM[1][3] = fma2(z1, wB.y, pM[1][3]);
            pP[0][0] = fma2(z2, wA.x, pP[0][0]);
            pP[0][1] = fma2(z2, wA.y, pP[0][1]);
            pP[0][2] = fma2(z2, wB.x, pP[0][2]);
            pP[0][3] = fma2(z2, wB.y, pP[0][3]);
            pP[1][0] = fma2(z3, wA.x, pP[1][0]);
            pP[1][1] = fma2(z3, wA.y, pP[1][1]);
            pP[1][2] = fma2(z3, wB.x, pP[1][2]);
            pP[1][3] = fma2(z3, wB.y, pP[1][3]);
        }
        // exchange: send partner-px partials, receive my-px partials
        #pragma unroll
        for (int c = 0; c < 4; c++) {
            int j = 4 * p + c;
            u64 fullA = add2(pM[0][c], xor1(pP[0][c]));
            u64 fullB = add2(pM[1][c], xor1(pP[1][c]));
            float s, o; upk(s_bn2[j], s, o);
            float bj = s_b2s[j];
            u64 wfj = s_wf[j];
            float f0, f1;
            upk(fullA, f0, f1);
            float pv = __cosf(f0 + f1 + bj);
            float qv = __cosf(fmaf(pv, s, o));
            dA = fma2(pk(qv, qv), wfj, dA);
            upk(fullB, f0, f1);
            pv = __cosf(f0 + f1 + bj);
            qv = __cosf(fmaf(pv, s, o));
            dB = fma2(pk(qv, qv), wfj, dB);
        }
    }

    u64 five = pk(STRENGTH, STRENGTH);
    u64 cfA = fma2(five, dA, pk(ca0, ca1));
    u64 cfB = fma2(five, dB, pk(cb0, cb1));

    float ra, rca, rb, rcb;
    upk(cfA, ra, rca);
    upk(cfB, rb, rcb);

    out[i]  = bil(img, ra, rca);
    out[ib] = bil(img, rb, rcb);
}

extern "C" void kernel_launch(void* const* d_in, const int* in_sizes, int n_in,
                              void* d_out, int out_size) {
    const float* x      = (const float*)d_in[0];
    const float* gen    = (const float*)d_in[1];
    const float* trans  = (const float*)d_in[2];
    const float* w0     = (const float*)d_in[3];
    const float* b0     = (const float*)d_in[4];
    const float* w1     = (const float*)d_in[5];
    const float* b1     = (const float*)d_in[6];
    const float* w2     = (const float*)d_in[7];
    const float* b2     = (const float*)d_in[8];
    const float* gam    = (const float*)d_in[9];
    const float* bet    = (const float*)d_in[10];
    const float* mean   = (const float*)d_in[11];
    const float* var    = (const float*)d_in[12];
    const float* wf     = (const float*)d_in[13];
    const float* img    = (const float*)d_in[14];
    float* out = (float*)d_out;

    prelude_kernel<<<1, 32>>>(gen, gam, bet, mean, var);
    rmodel_kernel<<<HALF / BLK, BLK>>>(x, trans, w0, b0, w1, b1, w2, b2,
                                       wf, img, out);
}

// round 12
// speedup vs baseline: 1.2745x; 1.2745x over previous
#include <cuda_runtime.h>
#include <cstdint>

#define H 512
#define TOT (16*256*256)
#define HALF (TOT/2)
#define SCALE_INV 0.1f
#define STRENGTH 5.0f

typedef unsigned long long u64;

// ---------- packed f32x2 helpers ----------
__device__ __forceinline__ u64 pk(float lo, float hi) {
    u64 r; asm("mov.b64 %0, {%1, %2};" : "=l"(r) : "f"(lo), "f"(hi)); return r;
}
__device__ __forceinline__ void upk(u64 v, float& lo, float& hi) {
    asm("mov.b64 {%0, %1}, %2;" : "=f"(lo), "=f"(hi) : "l"(v));
}
__device__ __forceinline__ u64 fma2(u64 a, u64 b, u64 c) {
    u64 d; asm("fma.rn.f32x2 %0, %1, %2, %3;" : "=l"(d) : "l"(a), "l"(b), "l"(c)); return d;
}
__device__ __forceinline__ u64 cos2(u64 v) {
    float lo, hi; upk(v, lo, hi);
    return pk(__cosf(lo), __cosf(hi));
}

// ---------- layer-1 weights in constant memory (raw w1 layout) ----------
// Warp-uniform, compile-time-indexed -> served by the constant-cache port,
// in parallel with the L1/shared crossbar that layer 2 uses.
__constant__ ulonglong2 c_w1[256];   // [k*8+q] = w1 row k, cols 4q..4q+3

// ---------- prelude results ----------
__device__ float g_A[4];
__device__ __align__(8) float g_bns[32];
__device__ __align__(8) float g_bno[32];

__global__ void prelude_kernel(const float* __restrict__ gen,
                               const float* __restrict__ gam,
                               const float* __restrict__ bet,
                               const float* __restrict__ mean,
                               const float* __restrict__ var) {
    int t = threadIdx.x;
    if (t == 0) {
        double m0 = gen[0], m1 = gen[1], m2 = gen[2], m3 = gen[3];
        double a0 = 1.0, a1 = 0.0, a2 = 0.0, a3 = 1.0;
        double t0 = 1.0, t1 = 0.0, t2 = 0.0, t3 = 1.0;
        for (int k = 1; k <= 18; k++) {
            double n0 = (t0 * m0 + t1 * m2) / k;
            double n1 = (t0 * m1 + t1 * m3) / k;
            double n2 = (t2 * m0 + t3 * m2) / k;
            double n3 = (t2 * m1 + t3 * m3) / k;
            t0 = n0; t1 = n1; t2 = n2; t3 = n3;
            a0 += n0; a1 += n1; a2 += n2; a3 += n3;
        }
        g_A[0] = (float)a0; g_A[1] = (float)a1;
        g_A[2] = (float)a2; g_A[3] = (float)a3;
    }
    if (t < 32) {
        float s = gam[t] * rsqrtf(var[t] + 0.001f);
        g_bns[t] = s;
        g_bno[t] = bet[t] - mean[t] * s;
    }
}

// ---------- bilinear sample ----------
__device__ __forceinline__ float bil(const float* __restrict__ img, float r, float c) {
    r = fminf(fmaxf(r, 0.0f), (float)(H - 1));
    c = fminf(fmaxf(c, 0.0f), (float)(H - 1));
    float rf = floorf(r), cf = floorf(c);
    int r0 = (int)rf, c0 = (int)cf;
    int r1 = min(r0 + 1, H - 1), c1 = min(c0 + 1, H - 1);
    float wr = r - rf, wc = c - cf;
    float v00 = __ldg(img + r0 * H + c0);
    float v01 = __ldg(img + r0 * H + c1);
    float v10 = __ldg(img + r1 * H + c0);
    float v11 = __ldg(img + r1 * H + c1);
    float top = v00 + wc * (v01 - v00);
    float bot = v10 + wc * (v11 - v10);
    return top + wr * (bot - top);
}

// ---------- main kernel (R6 structure; layer-1 weights from constant) ----------
// 2 px/thread, f32x2 lanes = two adjacent OUTPUT columns.
//  - layer0 fused into layer1 k-loop (y computed on the fly)
//  - layer1 weights: __constant__ (const port)   <- only change vs R6
//  - layer2 weights: shared (L1 crossbar), two column-halves, fused BN/cos/wf
#define BLK 128
__global__ __launch_bounds__(BLK, 4)
void rmodel_kernel(const float* __restrict__ x,
                   const float* __restrict__ trans,
                   const float* __restrict__ w0, const float* __restrict__ b0,
                   const float* __restrict__ b1,
                   const float* __restrict__ w2, const float* __restrict__ b2,
                   const float* __restrict__ wf,
                   const float* __restrict__ img,
                   float* __restrict__ out) {
    __shared__ ulonglong2 s_w2[256];   // [k*8+q] = w2 row k, cols 4q..4q+3
    __shared__ ulonglong2 s_l0[32];    // [k]: .x = dup w0[0][k], .y = dup w0[1][k]
    __shared__ u64 s_l0b[32];          // dup b0[k]
    __shared__ u64 s_b1[16], s_b2[16];
    __shared__ u64 s_bns[16], s_bno[16];
    __shared__ ulonglong2 s_wf[16];    // [j] = {wf rows 2j, 2j+1}

    int tid = threadIdx.x;
    {
        const ulonglong2* gw2 = (const ulonglong2*)w2;
        for (int e = tid; e < 256; e += BLK) s_w2[e] = gw2[e];
        if (tid < 32) {
            float wa = w0[tid], wb = w0[32 + tid], bb = b0[tid];
            s_l0[tid] = make_ulonglong2(pk(wa, wa), pk(wb, wb));
            s_l0b[tid] = pk(bb, bb);
        }
        if (tid < 16) {
            s_wf[tid]  = ((const ulonglong2*)wf)[tid];
            s_b1[tid]  = ((const u64*)b1)[tid];
            s_b2[tid]  = ((const u64*)b2)[tid];
            s_bns[tid] = pk(g_bns[2 * tid], g_bns[2 * tid + 1]);
            s_bno[tid] = pk(g_bno[2 * tid], g_bno[2 * tid + 1]);
        }
    }
    __syncthreads();

    int i = blockIdx.x * BLK + tid;           // pixels (i, i+HALF)
    int ib = i + HALF;

    float xa0 = __ldg(x + 3 * i),  xa1 = __ldg(x + 3 * i + 1);
    float xb0 = __ldg(x + 3 * ib), xb1 = __ldg(x + 3 * ib + 1);

    float A0 = g_A[0], A1 = g_A[1], A2 = g_A[2], A3 = g_A[3];
    float t0 = __ldg(trans), t1 = __ldg(trans + 1);

    float ca0 = fmaf(A0, xa0, fmaf(A1, xa1, t0));
    float ca1 = fmaf(A2, xa0, fmaf(A3, xa1, t1));
    float cb0 = fmaf(A0, xb0, fmaf(A1, xb1, t0));
    float cb1 = fmaf(A2, xb0, fmaf(A3, xb1, t1));

    // lanes of pa* = pixels {A, B}
    u64 pa0 = pk(ca0 * SCALE_INV, cb0 * SCALE_INV);
    u64 pa1 = pk(ca1 * SCALE_INV, cb1 * SCALE_INV);

    // ---- layer 1 (layer 0 fused into k-loop), weights from constant ----
    u64 accA[16], accB[16];
    #pragma unroll
    for (int jp = 0; jp < 16; jp++) { u64 b = s_b1[jp]; accA[jp] = b; accB[jp] = b; }

    #pragma unroll 4
    for (int k = 0; k < 32; k++) {
        ulonglong2 w0k = s_l0[k];
        u64 arg = fma2(pa0, w0k.x, fma2(pa1, w0k.y, s_l0b[k]));
        float uA, uB; upk(arg, uA, uB);
        float ykA = __cosf(uA), ykB = __cosf(uB);
        u64 da = pk(ykA, ykA), db = pk(ykB, ykB);
        #pragma unroll
        for (int q = 0; q < 8; q++) {
            ulonglong2 w = c_w1[k * 8 + q];
            accA[2 * q]     = fma2(da, w.x, accA[2 * q]);
            accA[2 * q + 1] = fma2(da, w.y, accA[2 * q + 1]);
            accB[2 * q]     = fma2(db, w.x, accB[2 * q]);
            accB[2 * q + 1] = fma2(db, w.y, accB[2 * q + 1]);
        }
    }

    // z = cos(acc), stored as f32 (acc regs freed after this)
    float zA[32], zB[32];
    #pragma unroll
    for (int jp = 0; jp < 16; jp++) {
        float u, v;
        upk(accA[jp], u, v); zA[2 * jp] = __cosf(u); zA[2 * jp + 1] = __cosf(v);
        upk(accB[jp], u, v); zB[2 * jp] = __cosf(u); zB[2 * jp + 1] = __cosf(v);
    }

    // ---- layer 2 in two column-halves + fused BN/cos + partial wf proj ----
    u64 dA = 0ull, dB = 0ull;
    #pragma unroll
    for (int h = 0; h < 2; h++) {
        u64 a2A[8], a2B[8];
        #pragma unroll
        for (int jp = 0; jp < 8; jp++) { u64 b = s_b2[8 * h + jp]; a2A[jp] = b; a2B[jp] = b; }
        #pragma unroll
        for (int k = 0; k < 32; k++) {
            u64 da = pk(zA[k], zA[k]);
            u64 db = pk(zB[k], zB[k]);
            #pragma unroll
            for (int q = 0; q < 4; q++) {
                ulonglong2 w = s_w2[k * 8 + 4 * h + q];
                a2A[2 * q]     = fma2(da, w.x, a2A[2 * q]);
                a2A[2 * q + 1] = fma2(da, w.y, a2A[2 * q + 1]);
                a2B[2 * q]     = fma2(db, w.x, a2B[2 * q]);
                a2B[2 * q + 1] = fma2(db, w.y, a2B[2 * q + 1]);
            }
        }
        #pragma unroll
        for (int jp = 0; jp < 8; jp++) {
            int j = 8 * h + jp;                 // global column-pair
            u64 s = s_bns[j], o = s_bno[j];
            ulonglong2 wfp = s_wf[j];           // wf rows 2j, 2j+1
            u64 qa = cos2(fma2(cos2(a2A[jp]), s, o));
            u64 qb = cos2(fma2(cos2(a2B[jp]), s, o));
            float f0, f1;
            upk(qa, f0, f1);
            dA = fma2(pk(f0, f0), wfp.x, dA);
            dA = fma2(pk(f1, f1), wfp.y, dA);
            upk(qb, f0, f1);
            dB = fma2(pk(f0, f0), wfp.x, dB);
            dB = fma2(pk(f1, f1), wfp.y, dB);
        }
    }

    u64 five = pk(STRENGTH, STRENGTH);
    u64 cfA = fma2(five, dA, pk(ca0, ca1));
    u64 cfB = fma2(five, dB, pk(cb0, cb1));

    float ra, rca, rb, rcb;
    upk(cfA, ra, rca);
    upk(cfB, rb, rcb);

    out[i]  = bil(img, ra, rca);
    out[ib] = bil(img, rb, rcb);
}

extern "C" void kernel_launch(void* const* d_in, const int* in_sizes, int n_in,
                              void* d_out, int out_size) {
    const float* x      = (const float*)d_in[0];
    const float* gen    = (const float*)d_in[1];
    const float* trans  = (const float*)d_in[2];
    const float* w0     = (const float*)d_in[3];
    const float* b0     = (const float*)d_in[4];
    const float* w1     = (const float*)d_in[5];
    const float* b1     = (const float*)d_in[6];
    const float* w2     = (const float*)d_in[7];
    const float* b2     = (const float*)d_in[8];
    const float* gam    = (const float*)d_in[9];
    const float* bet    = (const float*)d_in[10];
    const float* mean   = (const float*)d_in[11];
    const float* var    = (const float*)d_in[12];
    const float* wf     = (const float*)d_in[13];
    const float* img    = (const float*)d_in[14];
    float* out = (float*)d_out;

    // Stage layer-1 weights into constant memory (async D2D, graph-capturable)
    cudaMemcpyToSymbolAsync(c_w1, w1, 1024 * sizeof(float), 0,
                            cudaMemcpyDeviceToDevice);

    prelude_kernel<<<1, 32>>>(gen, gam, bet, mean, var);
    rmodel_kernel<<<HALF / BLK, BLK>>>(x, trans, w0, b0, b1, w2, b2,
                                       wf, img, out);
}